// round 4
// baseline (speedup 1.0000x reference)
#include <cuda_runtime.h>
#include <math.h>

// Problem constants
#define Tn 128
#define Bn 2048
#define Hn 256
#define In0 18

// Tiling
#define KC 16
#define NTHREADS 256
#define HS_LD 68    // smem stride for activation tile (16B-aligned friendly, bank spread)
#define WS_LD 196   // smem stride for weight tile (<=192 gate-cols + pad)

typedef unsigned long long u64;

// Ring buffers for hidden state (depth 2).
__device__ float g_h1[2][Bn * Hn];
__device__ float g_h2[2][Bn * Hn];

__device__ __forceinline__ float sigf(float x) { return 1.f / (1.f + expf(-x)); }

// packed 2-wide fp32 FMA (FFMA2) — only reachable via PTX
__device__ __forceinline__ void ffma2(u64& d, u64 a, u64 b) {
    asm("fma.rn.f32x2 %0, %1, %2, %0;" : "+l"(d) : "l"(a), "l"(b));
}
__device__ __forceinline__ u64 dup2(float x) {
    u64 r; asm("mov.b64 %0, {%1, %1};" : "=l"(r) : "f"(x)); return r;
}
__device__ __forceinline__ float2 unpack2(u64 v) {
    float2 f; asm("mov.b64 {%0, %1}, %2;" : "=f"(f.x), "=f"(f.y) : "l"(v)); return f;
}

// One accumulation stream over K:
//   acc{R,Z,a3}[ii][jp] (+)= A[b0+batch][k] * W[gate*Hn + j0+unit][k]
// BNT = units per tile (32 or 64), II = batch rows per thread (64/ (NTHREADS/(BNT/4)) ).
// Accumulators are f32x2 pairs along the unit dimension.
template<int BNT, int II>
__device__ __forceinline__ void stream_mm(
    const float* __restrict__ A, int lda, int K,
    const float* __restrict__ W, int ldw,
    int b0, int j0, int tid, bool vec,
    float (*hs)[HS_LD], float (*ws)[WS_LD],
    u64 (&aR)[II][2], u64 (&aZ)[II][2], u64 (&a3)[II][2])
{
    constexpr int WSLOTS = 3 * BNT * 4;                       // float4 slots per chunk
    constexpr int NWL = (WSLOTS + NTHREADS - 1) / NTHREADS;   // 3 (BNT=64) or 2 (BNT=32)
    const int tx = tid % (BNT / 4);
    const int ty = tid / (BNT / 4);
    const int arow = tid >> 2;    // 0..63 (batch row for staging)
    const int akv  = tid & 3;     // k-quad
    const int nch = (K + KC - 1) / KC;

    float fa[4];
    float fw[NWL][4];

    auto fetch = [&](int k0) {
        // activations
        if (vec) {
            const float4 t4 = *(const float4*)(A + (size_t)(b0 + arow) * lda + k0 + akv * 4);
            fa[0] = t4.x; fa[1] = t4.y; fa[2] = t4.z; fa[3] = t4.w;
        } else {
            #pragma unroll
            for (int i = 0; i < 4; ++i) {
                const int k = k0 + akv * 4 + i;
                fa[i] = (k < K) ? A[(size_t)(b0 + arow) * lda + k] : 0.f;
            }
        }
        // weights (rows 0..3*BNT-1 map gate-major: row = g*BNT + jr)
        #pragma unroll
        for (int s = 0; s < NWL; ++s) {
            const int slot = tid + s * NTHREADS;
            if (slot < WSLOTS) {
                const int row = slot >> 2, kv = slot & 3;
                const int g = row / BNT, jr = row % BNT;
                const float* wr = W + (size_t)(g * Hn + j0 + jr) * ldw;
                if (vec) {
                    const float4 w4 = *(const float4*)(wr + k0 + kv * 4);
                    fw[s][0] = w4.x; fw[s][1] = w4.y; fw[s][2] = w4.z; fw[s][3] = w4.w;
                } else {
                    #pragma unroll
                    for (int i = 0; i < 4; ++i) {
                        const int k = k0 + kv * 4 + i;
                        fw[s][i] = (k < K) ? wr[k] : 0.f;
                    }
                }
            }
        }
    };

    fetch(0);

    for (int c = 0; c < nch; ++c) {
        __syncthreads();   // previous user done with smem
        #pragma unroll
        for (int i = 0; i < 4; ++i) hs[akv * 4 + i][arow] = fa[i];
        #pragma unroll
        for (int s = 0; s < NWL; ++s) {
            const int slot = tid + s * NTHREADS;
            if (slot < WSLOTS) {
                const int row = slot >> 2, kv = slot & 3;
                #pragma unroll
                for (int i = 0; i < 4; ++i) ws[kv * 4 + i][row] = fw[s][i];
            }
        }
        __syncthreads();

        if (c + 1 < nch) fetch((c + 1) * KC);

        // FFMA2 core
        #pragma unroll
        for (int k = 0; k < KC; ++k) {
            u64 hd[II];
            if (II == 4) {
                const float4 hb = *(const float4*)&hs[k][ty * 4];
                hd[0] = dup2(hb.x); hd[1] = dup2(hb.y); hd[2] = dup2(hb.z); hd[3] = dup2(hb.w);
            } else {
                const float2 hb = *(const float2*)&hs[k][ty * 2];
                hd[0] = dup2(hb.x); hd[1] = dup2(hb.y);
            }
            const ulonglong2 wr = *(const ulonglong2*)&ws[k][0 * BNT + tx * 4];
            const ulonglong2 wz = *(const ulonglong2*)&ws[k][1 * BNT + tx * 4];
            const ulonglong2 wn = *(const ulonglong2*)&ws[k][2 * BNT + tx * 4];
            #pragma unroll
            for (int ii = 0; ii < II; ++ii) {
                ffma2(aR[ii][0], hd[ii], wr.x); ffma2(aR[ii][1], hd[ii], wr.y);
                ffma2(aZ[ii][0], hd[ii], wz.x); ffma2(aZ[ii][1], hd[ii], wz.y);
                ffma2(a3[ii][0], hd[ii], wn.x); ffma2(a3[ii][1], hd[ii], wn.y);
            }
        }
    }
}

template<int BNT, int II>
__device__ __forceinline__ void gru_epilogue(
    const float* __restrict__ bih, const float* __restrict__ bhh,
    const float* __restrict__ hprev, float* __restrict__ hout,
    int b0, int j0, int tid,
    u64 (&aR)[II][2], u64 (&aZ)[II][2], u64 (&aXN)[II][2], u64 (&aHN)[II][2])
{
    const int tx = tid % (BNT / 4);
    const int ty = tid / (BNT / 4);
    #pragma unroll
    for (int ii = 0; ii < II; ++ii) {
        const int b = b0 + ty * II + ii;
        #pragma unroll
        for (int jp = 0; jp < 2; ++jp) {
            const float2 r2  = unpack2(aR[ii][jp]);
            const float2 z2  = unpack2(aZ[ii][jp]);
            const float2 xn2 = unpack2(aXN[ii][jp]);
            const float2 hn2 = unpack2(aHN[ii][jp]);
            #pragma unroll
            for (int jh = 0; jh < 2; ++jh) {
                const int j = j0 + tx * 4 + jp * 2 + jh;
                const float br = bih[j] + bhh[j];
                const float bz = bih[Hn + j] + bhh[Hn + j];
                const float rv = jh ? r2.y : r2.x;
                const float zv = jh ? z2.y : z2.x;
                const float xnv = jh ? xn2.y : xn2.x;
                const float hnv = jh ? hn2.y : hn2.x;
                const float r = sigf(rv + br);
                const float z = sigf(zv + bz);
                const float n = tanhf(xnv + bih[2 * Hn + j] + r * (hnv + bhh[2 * Hn + j]));
                const float hp = hprev[(size_t)b * Hn + j];
                hout[(size_t)b * Hn + j] = (1.f - z) * n + z * hp;
            }
        }
    }
}

// Pipelined super-step l: CTAs [0,128) run layer0 at t=l (64x64 tiles),
// CTAs [128,384) run layer1 at t=l-1 (64x32 tiles) -> near-equal work per CTA.
__global__ void __launch_bounds__(NTHREADS, 2)
gru_step_kernel(const float* __restrict__ x,
                const float* __restrict__ Wih0, const float* __restrict__ Whh0,
                const float* __restrict__ bih0, const float* __restrict__ bhh0,
                const float* __restrict__ Wih1, const float* __restrict__ Whh1,
                const float* __restrict__ bih1, const float* __restrict__ bhh1,
                int l)
{
    __shared__ float hs[KC][HS_LD];
    __shared__ float ws[KC][WS_LD];

    const int cta = blockIdx.x;
    const bool L1 = (cta >= 128);
    const int t = L1 ? (l - 1) : l;
    if (t < 0 || t >= Tn) return;
    const int tid = threadIdx.x;

    if (!L1) {
        const int b0 = (cta >> 2) * 64;
        const int j0 = (cta & 3) * 64;
        u64 aR[4][2] = {}, aZ[4][2] = {}, aXN[4][2] = {}, aHN[4][2] = {};
        const float* xin   = x + (size_t)t * Bn * In0;
        const float* hprev = g_h1[(t + 1) & 1];
        float*       hout  = g_h1[t & 1];
        stream_mm<64, 4>(xin, In0, In0, Wih0, In0, b0, j0, tid, false, hs, ws, aR, aZ, aXN);
        stream_mm<64, 4>(hprev, Hn, Hn, Whh0, Hn, b0, j0, tid, true, hs, ws, aR, aZ, aHN);
        gru_epilogue<64, 4>(bih0, bhh0, hprev, hout, b0, j0, tid, aR, aZ, aXN, aHN);
    } else {
        const int idx = cta - 128;           // 0..255
        const int b0 = (idx >> 3) * 64;      // 32 batch tiles
        const int j0 = (idx & 7) * 32;       // 8 unit tiles
        u64 aR[2][2] = {}, aZ[2][2] = {}, aXN[2][2] = {}, aHN[2][2] = {};
        const float* xin   = g_h1[t & 1];    // h1[t], produced by previous launch
        const float* hprev = g_h2[(t + 1) & 1];
        float*       hout  = g_h2[t & 1];
        stream_mm<32, 2>(xin, Hn, Hn, Wih1, Hn, b0, j0, tid, true, hs, ws, aR, aZ, aXN);
        stream_mm<32, 2>(hprev, Hn, Hn, Whh1, Hn, b0, j0, tid, true, hs, ws, aR, aZ, aHN);
        gru_epilogue<32, 2>(bih1, bhh1, hprev, hout, b0, j0, tid, aR, aZ, aXN, aHN);
    }
}

// Final FC + sigmoid*2-1 on h2[T-1]. One warp per batch row.
__global__ void fc_kernel(const float* __restrict__ fcw, const float* __restrict__ fcb,
                          float* __restrict__ out)
{
    const int warp = (blockIdx.x * blockDim.x + threadIdx.x) >> 5;
    const int lane = threadIdx.x & 31;
    if (warp >= Bn) return;
    const float* h = g_h2[(Tn - 1) & 1] + (size_t)warp * Hn;
    float a0 = 0.f, a1 = 0.f, a2 = 0.f, a3 = 0.f;
    for (int k = lane; k < Hn; k += 32) {
        const float hv = h[k];
        a0 = fmaf(hv, fcw[k], a0);
        a1 = fmaf(hv, fcw[Hn + k], a1);
        a2 = fmaf(hv, fcw[2 * Hn + k], a2);
        a3 = fmaf(hv, fcw[3 * Hn + k], a3);
    }
    #pragma unroll
    for (int s = 16; s; s >>= 1) {
        a0 += __shfl_xor_sync(0xFFFFFFFFu, a0, s);
        a1 += __shfl_xor_sync(0xFFFFFFFFu, a1, s);
        a2 += __shfl_xor_sync(0xFFFFFFFFu, a2, s);
        a3 += __shfl_xor_sync(0xFFFFFFFFu, a3, s);
    }
    if (lane == 0) {
        out[warp * 4 + 0] = 2.f * sigf(a0 + fcb[0]) - 1.f;
        out[warp * 4 + 1] = 2.f * sigf(a1 + fcb[1]) - 1.f;
        out[warp * 4 + 2] = 2.f * sigf(a2 + fcb[2]) - 1.f;
        out[warp * 4 + 3] = 2.f * sigf(a3 + fcb[3]) - 1.f;
    }
}

extern "C" void kernel_launch(void* const* d_in, const int* in_sizes, int n_in,
                              void* d_out, int out_size)
{
    const float* x    = (const float*)d_in[0];
    const float* Wih0 = (const float*)d_in[1];
    const float* Whh0 = (const float*)d_in[2];
    const float* bih0 = (const float*)d_in[3];
    const float* bhh0 = (const float*)d_in[4];
    const float* Wih1 = (const float*)d_in[5];
    const float* Whh1 = (const float*)d_in[6];
    const float* bih1 = (const float*)d_in[7];
    const float* bhh1 = (const float*)d_in[8];
    const float* fcw  = (const float*)d_in[9];
    const float* fcb  = (const float*)d_in[10];
    float* out = (float*)d_out;
    (void)in_sizes; (void)n_in; (void)out_size;

    // zero the "previous state" slots used at t=0 (slot (0+1)&1 == 1)
    void *p1 = nullptr, *p2 = nullptr;
    cudaGetSymbolAddress(&p1, g_h1);
    cudaGetSymbolAddress(&p2, g_h2);
    cudaMemsetAsync((char*)p1 + sizeof(float) * (size_t)Bn * Hn, 0,
                    sizeof(float) * (size_t)Bn * Hn, 0);
    cudaMemsetAsync((char*)p2 + sizeof(float) * (size_t)Bn * Hn, 0,
                    sizeof(float) * (size_t)Bn * Hn, 0);

    for (int l = 0; l <= Tn; ++l) {
        gru_step_kernel<<<384, NTHREADS>>>(x, Wih0, Whh0, bih0, bhh0,
                                           Wih1, Whh1, bih1, bhh1, l);
    }

    fc_kernel<<<(Bn * 32) / 256, 256>>>(fcw, fcb, out);
}

// round 5
// speedup vs baseline: 1.3010x; 1.3010x over previous
#include <cuda_runtime.h>
#include <cuda_bf16.h>
#include <math.h>

// Problem constants
#define Tn 128
#define Bn 2048
#define Hn 256
#define In0 18
#define KP0 32          // x K padded to 32 (2 chunks of 16)
#define G3H 768         // 3*Hn

typedef unsigned int u32;

// ---------------- device global scratch (no alloc allowed) ----------------
__device__ float          g_h1f[2][Bn * Hn];
__device__ float          g_h2f[2][Bn * Hn];
__device__ __nv_bfloat16  g_h1h[2][Bn * Hn], g_h1l[2][Bn * Hn];
__device__ __nv_bfloat16  g_h2h[2][Bn * Hn], g_h2l[2][Bn * Hn];
__device__ __nv_bfloat16  g_xh[(size_t)Tn * Bn * KP0], g_xl[(size_t)Tn * Bn * KP0];
__device__ __nv_bfloat16  g_wih0h[G3H * KP0], g_wih0l[G3H * KP0];
__device__ __nv_bfloat16  g_whh0h[G3H * Hn],  g_whh0l[G3H * Hn];
__device__ __nv_bfloat16  g_wih1h[G3H * Hn],  g_wih1l[G3H * Hn];
__device__ __nv_bfloat16  g_whh1h[G3H * Hn],  g_whh1l[G3H * Hn];

__device__ __forceinline__ float sigf(float x) { return 1.f / (1.f + expf(-x)); }

// mma.sync m16n8k16 row.col f32.bf16.bf16.f32
__device__ __forceinline__ void mma16816(float* d, const u32* a, const u32* b) {
    asm("mma.sync.aligned.m16n8k16.row.col.f32.bf16.bf16.f32 "
        "{%0,%1,%2,%3},{%4,%5,%6,%7},{%8,%9},{%0,%1,%2,%3};"
        : "+f"(d[0]), "+f"(d[1]), "+f"(d[2]), "+f"(d[3])
        : "r"(a[0]), "r"(a[1]), "r"(a[2]), "r"(a[3]), "r"(b[0]), "r"(b[1]));
}

// ---------------- one K-stream of the tile GEMM ----------------
// CTA: 256 threads = 8 warps, warp grid 4(m) x 2(n).
// MT = m16-tiles per warp (2 -> CTA M=128, 1 -> CTA M=64). Units per CTA: 64 (192 gate cols).
// A: [M rows][lda] bf16 (hi & lo), W: [768 rows][ldw] bf16 (hi & lo), rows g*256 + j0 + jr.
// smem tiles hold one k16 chunk as u32 k-pairs: sA[M][8], sW[192][8].
template<int MT>
__device__ __forceinline__ void gru_stream(
    const __nv_bfloat16* __restrict__ Ah, const __nv_bfloat16* __restrict__ Al, int lda, int nch,
    const __nv_bfloat16* __restrict__ Wh, const __nv_bfloat16* __restrict__ Wl, int ldw, int j0,
    u32* __restrict__ sAh, u32* __restrict__ sAl, u32* __restrict__ sWh, u32* __restrict__ sWl,
    float (&aR)[MT][4][4], float (&aZ)[MT][4][4], float (&aN)[MT][4][4])
{
    const int tid = threadIdx.x;
    const int lane = tid & 31, wid = tid >> 5;
    const int wm = wid >> 1, wn = wid & 1;
    const bool aval = (MT == 2) || (tid < 128);
    const int arow = tid >> 1, half = tid & 1;      // A slot: row, 8-elem half
    const int wrow0 = tid >> 1;                      // W slots 0..191 (x2 halves)
    const int wrow1 = 128 + (tid >> 1);              // second W slot (tid<128)
    const int grow0 = (wrow0 >> 6) * Hn + j0 + (wrow0 & 63);
    const int grow1 = (wrow1 >> 6) * Hn + j0 + (wrow1 & 63);

    uint4 fah, fal, fwh0, fwl0, fwh1, fwl1;
    auto fetch = [&](int c) {
        const int k0 = c * 16 + half * 8;
        if (aval) {
            fah = *(const uint4*)(Ah + (size_t)arow * lda + k0);
            fal = *(const uint4*)(Al + (size_t)arow * lda + k0);
        }
        fwh0 = *(const uint4*)(Wh + (size_t)grow0 * ldw + k0);
        fwl0 = *(const uint4*)(Wl + (size_t)grow0 * ldw + k0);
        if (tid < 128) {
            fwh1 = *(const uint4*)(Wh + (size_t)grow1 * ldw + k0);
            fwl1 = *(const uint4*)(Wl + (size_t)grow1 * ldw + k0);
        }
    };

    fetch(0);
    for (int c = 0; c < nch; ++c) {
        __syncthreads();
        if (aval) {
            *(uint4*)&sAh[arow * 8 + half * 4] = fah;
            *(uint4*)&sAl[arow * 8 + half * 4] = fal;
        }
        *(uint4*)&sWh[wrow0 * 8 + half * 4] = fwh0;
        *(uint4*)&sWl[wrow0 * 8 + half * 4] = fwl0;
        if (tid < 128) {
            *(uint4*)&sWh[wrow1 * 8 + half * 4] = fwh1;
            *(uint4*)&sWl[wrow1 * 8 + half * 4] = fwl1;
        }
        __syncthreads();
        if (c + 1 < nch) fetch(c + 1);

        // A fragments for this chunk
        u32 ah[MT][4], al[MT][4];
        #pragma unroll
        for (int mt = 0; mt < MT; ++mt) {
            const int r = wm * (MT * 16) + mt * 16 + (lane >> 2);
            const int kq = lane & 3;
            ah[mt][0] = sAh[r * 8 + kq];       ah[mt][1] = sAh[(r + 8) * 8 + kq];
            ah[mt][2] = sAh[r * 8 + kq + 4];   ah[mt][3] = sAh[(r + 8) * 8 + kq + 4];
            al[mt][0] = sAl[r * 8 + kq];       al[mt][1] = sAl[(r + 8) * 8 + kq];
            al[mt][2] = sAl[r * 8 + kq + 4];   al[mt][3] = sAl[(r + 8) * 8 + kq + 4];
        }
        // 3 gates x 4 n-tiles, split passes hi*hi + lo*hi + hi*lo
        #pragma unroll
        for (int g = 0; g < 3; ++g) {
            float (*ac)[4][4] = (g == 0) ? aR : (g == 1) ? aZ : aN;
            #pragma unroll
            for (int nt = 0; nt < 4; ++nt) {
                const int col = g * 64 + wn * 32 + nt * 8 + (lane >> 2);
                const int kq = lane & 3;
                u32 bh[2] = { sWh[col * 8 + kq], sWh[col * 8 + kq + 4] };
                u32 bl[2] = { sWl[col * 8 + kq], sWl[col * 8 + kq + 4] };
                #pragma unroll
                for (int mt = 0; mt < MT; ++mt) {
                    mma16816(ac[mt][nt], ah[mt], bh);
                    mma16816(ac[mt][nt], al[mt], bh);
                    mma16816(ac[mt][nt], ah[mt], bl);
                }
            }
        }
    }
}

// ---------------- GRU gate epilogue ----------------
template<int MT>
__device__ __forceinline__ void gru_epi(
    const float* __restrict__ bih, const float* __restrict__ bhh,
    const float* __restrict__ hpf, float* __restrict__ hof,
    __nv_bfloat16* __restrict__ hoh, __nv_bfloat16* __restrict__ hol,
    int b0, int j0,
    float (&aR)[MT][4][4], float (&aZ)[MT][4][4], float (&aXN)[MT][4][4], float (&aHN)[MT][4][4])
{
    const int tid = threadIdx.x, lane = tid & 31, wid = tid >> 5;
    const int wm = wid >> 1, wn = wid & 1;
    #pragma unroll
    for (int nt = 0; nt < 4; ++nt) {
        #pragma unroll
        for (int jj = 0; jj < 2; ++jj) {
            const int j = j0 + wn * 32 + nt * 8 + 2 * (lane & 3) + jj;
            const float br  = bih[j] + bhh[j];
            const float bz  = bih[Hn + j] + bhh[Hn + j];
            const float bxn = bih[2 * Hn + j];
            const float bhn = bhh[2 * Hn + j];
            #pragma unroll
            for (int mt = 0; mt < MT; ++mt) {
                #pragma unroll
                for (int rr = 0; rr < 2; ++rr) {
                    const int b = b0 + wm * (MT * 16) + mt * 16 + (lane >> 2) + rr * 8;
                    const int o = rr * 2 + jj;
                    const float r = sigf(aR[mt][nt][o] + br);
                    const float z = sigf(aZ[mt][nt][o] + bz);
                    const float n = tanhf(aXN[mt][nt][o] + bxn + r * (aHN[mt][nt][o] + bhn));
                    const float hp = hpf[(size_t)b * Hn + j];
                    const float h = (1.f - z) * n + z * hp;
                    hof[(size_t)b * Hn + j] = h;
                    const __nv_bfloat16 hi = __float2bfloat16(h);
                    hoh[(size_t)b * Hn + j] = hi;
                    hol[(size_t)b * Hn + j] = __float2bfloat16(h - __bfloat162float(hi));
                }
            }
        }
    }
}

// ---------------- pipelined super-step ----------------
// CTAs 0..63: layer0 at t=l (tiles 128 batch x 64 units).
// CTAs 64..191: layer1 at t=l-1 (tiles 64 batch x 64 units).
__global__ void __launch_bounds__(256)
gru_step(const float* __restrict__ bih0, const float* __restrict__ bhh0,
         const float* __restrict__ bih1, const float* __restrict__ bhh1, int l)
{
    __shared__ u32 sAh[128 * 8], sAl[128 * 8], sWh[192 * 8], sWl[192 * 8];
    const int cta = blockIdx.x;

    if (cta < 64) {
        const int t = l;
        if (t >= Tn) return;
        const int b0 = (cta >> 2) * 128, j0 = (cta & 3) * 64;
        const int pv = (t + 1) & 1, cu = t & 1;
        float aR[2][4][4] = {}, aZ[2][4][4] = {}, aXN[2][4][4] = {}, aHN[2][4][4] = {};
        gru_stream<2>(g_xh + ((size_t)t * Bn + b0) * KP0, g_xl + ((size_t)t * Bn + b0) * KP0,
                      KP0, 2, g_wih0h, g_wih0l, KP0, j0, sAh, sAl, sWh, sWl, aR, aZ, aXN);
        gru_stream<2>(g_h1h[pv] + (size_t)b0 * Hn, g_h1l[pv] + (size_t)b0 * Hn,
                      Hn, 16, g_whh0h, g_whh0l, Hn, j0, sAh, sAl, sWh, sWl, aR, aZ, aHN);
        gru_epi<2>(bih0, bhh0, g_h1f[pv], g_h1f[cu], g_h1h[cu], g_h1l[cu], b0, j0,
                   aR, aZ, aXN, aHN);
    } else {
        const int t = l - 1;
        if (t < 0) return;
        const int idx = cta - 64;                 // 0..127
        const int b0 = (idx >> 2) * 64, j0 = (idx & 3) * 64;
        const int pv = (t + 1) & 1, cu = t & 1;
        float aR[1][4][4] = {}, aZ[1][4][4] = {}, aXN[1][4][4] = {}, aHN[1][4][4] = {};
        gru_stream<1>(g_h1h[cu] + (size_t)b0 * Hn, g_h1l[cu] + (size_t)b0 * Hn,
                      Hn, 16, g_wih1h, g_wih1l, Hn, j0, sAh, sAl, sWh, sWl, aR, aZ, aXN);
        gru_stream<1>(g_h2h[pv] + (size_t)b0 * Hn, g_h2l[pv] + (size_t)b0 * Hn,
                      Hn, 16, g_whh1h, g_whh1l, Hn, j0, sAh, sAl, sWh, sWl, aR, aZ, aHN);
        gru_epi<1>(bih1, bhh1, g_h2f[pv], g_h2f[cu], g_h2h[cu], g_h2l[cu], b0, j0,
                   aR, aZ, aXN, aHN);
    }
}

// ---------------- prologue: fp32 -> bf16 hi/lo splits ----------------
__global__ void split_plain(const float* __restrict__ src,
                            __nv_bfloat16* __restrict__ hi, __nv_bfloat16* __restrict__ lo, int n)
{
    const int i = blockIdx.x * blockDim.x + threadIdx.x;
    if (i >= n) return;
    const float v = src[i];
    const __nv_bfloat16 h = __float2bfloat16(v);
    hi[i] = h;
    lo[i] = __float2bfloat16(v - __bfloat162float(h));
}

__global__ void split_pad(const float* __restrict__ src,
                          __nv_bfloat16* __restrict__ hi, __nv_bfloat16* __restrict__ lo,
                          int rows, int K, int Kp)
{
    const int i = blockIdx.x * blockDim.x + threadIdx.x;
    if (i >= rows * Kp) return;
    const int r = i / Kp, k = i - r * Kp;
    const float v = (k < K) ? src[(size_t)r * K + k] : 0.f;
    const __nv_bfloat16 h = __float2bfloat16(v);
    hi[i] = h;
    lo[i] = __float2bfloat16(v - __bfloat162float(h));
}

// ---------------- final FC + sigmoid*2-1 ----------------
__global__ void fc_kernel(const float* __restrict__ fcw, const float* __restrict__ fcb,
                          float* __restrict__ out)
{
    const int warp = (blockIdx.x * blockDim.x + threadIdx.x) >> 5;
    const int lane = threadIdx.x & 31;
    if (warp >= Bn) return;
    const float* h = g_h2f[(Tn - 1) & 1] + (size_t)warp * Hn;
    float a0 = 0.f, a1 = 0.f, a2 = 0.f, a3 = 0.f;
    for (int k = lane; k < Hn; k += 32) {
        const float hv = h[k];
        a0 = fmaf(hv, fcw[k], a0);
        a1 = fmaf(hv, fcw[Hn + k], a1);
        a2 = fmaf(hv, fcw[2 * Hn + k], a2);
        a3 = fmaf(hv, fcw[3 * Hn + k], a3);
    }
    #pragma unroll
    for (int s = 16; s; s >>= 1) {
        a0 += __shfl_xor_sync(0xFFFFFFFFu, a0, s);
        a1 += __shfl_xor_sync(0xFFFFFFFFu, a1, s);
        a2 += __shfl_xor_sync(0xFFFFFFFFu, a2, s);
        a3 += __shfl_xor_sync(0xFFFFFFFFu, a3, s);
    }
    if (lane == 0) {
        out[warp * 4 + 0] = 2.f * sigf(a0 + fcb[0]) - 1.f;
        out[warp * 4 + 1] = 2.f * sigf(a1 + fcb[1]) - 1.f;
        out[warp * 4 + 2] = 2.f * sigf(a2 + fcb[2]) - 1.f;
        out[warp * 4 + 3] = 2.f * sigf(a3 + fcb[3]) - 1.f;
    }
}

extern "C" void kernel_launch(void* const* d_in, const int* in_sizes, int n_in,
                              void* d_out, int out_size)
{
    const float* x    = (const float*)d_in[0];
    const float* Wih0 = (const float*)d_in[1];
    const float* Whh0 = (const float*)d_in[2];
    const float* bih0 = (const float*)d_in[3];
    const float* bhh0 = (const float*)d_in[4];
    const float* Wih1 = (const float*)d_in[5];
    const float* Whh1 = (const float*)d_in[6];
    const float* bih1 = (const float*)d_in[7];
    const float* bhh1 = (const float*)d_in[8];
    const float* fcw  = (const float*)d_in[9];
    const float* fcb  = (const float*)d_in[10];
    float* out = (float*)d_out;
    (void)in_sizes; (void)n_in; (void)out_size;

    // --- prologue: split x and weights into bf16 hi/lo (constant per call) ---
    {
        void *xh, *xl, *w0h, *w0l, *h0h, *h0l, *w1h, *w1l, *h1h, *h1l;
        cudaGetSymbolAddress(&xh, g_xh);    cudaGetSymbolAddress(&xl, g_xl);
        cudaGetSymbolAddress(&w0h, g_wih0h); cudaGetSymbolAddress(&w0l, g_wih0l);
        cudaGetSymbolAddress(&h0h, g_whh0h); cudaGetSymbolAddress(&h0l, g_whh0l);
        cudaGetSymbolAddress(&w1h, g_wih1h); cudaGetSymbolAddress(&w1l, g_wih1l);
        cudaGetSymbolAddress(&h1h, g_whh1h); cudaGetSymbolAddress(&h1l, g_whh1l);

        const int nx = Tn * Bn * KP0;
        split_pad<<<(nx + 255) / 256, 256>>>(x, (__nv_bfloat16*)xh, (__nv_bfloat16*)xl,
                                             Tn * Bn, In0, KP0);
        split_pad<<<(G3H * KP0 + 255) / 256, 256>>>(Wih0, (__nv_bfloat16*)w0h, (__nv_bfloat16*)w0l,
                                                    G3H, In0, KP0);
        const int nw = G3H * Hn;
        split_plain<<<(nw + 255) / 256, 256>>>(Whh0, (__nv_bfloat16*)h0h, (__nv_bfloat16*)h0l, nw);
        split_plain<<<(nw + 255) / 256, 256>>>(Wih1, (__nv_bfloat16*)w1h, (__nv_bfloat16*)w1l, nw);
        split_plain<<<(nw + 255) / 256, 256>>>(Whh1, (__nv_bfloat16*)h1h, (__nv_bfloat16*)h1l, nw);
    }

    // --- zero the "previous" ring slot (slot 1) for all state buffers ---
    {
        void *p;
        const size_t nf = sizeof(float) * (size_t)Bn * Hn;
        const size_t nb = sizeof(__nv_bfloat16) * (size_t)Bn * Hn;
        cudaGetSymbolAddress(&p, g_h1f); cudaMemsetAsync((char*)p + nf, 0, nf, 0);
        cudaGetSymbolAddress(&p, g_h2f); cudaMemsetAsync((char*)p + nf, 0, nf, 0);
        cudaGetSymbolAddress(&p, g_h1h); cudaMemsetAsync((char*)p + nb, 0, nb, 0);
        cudaGetSymbolAddress(&p, g_h1l); cudaMemsetAsync((char*)p + nb, 0, nb, 0);
        cudaGetSymbolAddress(&p, g_h2h); cudaMemsetAsync((char*)p + nb, 0, nb, 0);
        cudaGetSymbolAddress(&p, g_h2l); cudaMemsetAsync((char*)p + nb, 0, nb, 0);
    }

    // --- pipelined scan: layer0 at t=l, layer1 at t=l-1 ---
    for (int l = 0; l <= Tn; ++l) {
        gru_step<<<192, 256>>>(bih0, bhh0, bih1, bhh1, l);
    }

    fc_kernel<<<(Bn * 32) / 256, 256>>>(fcw, fcb, out);
}

// round 6
// speedup vs baseline: 2.6866x; 2.0651x over previous
#include <cuda_runtime.h>
#include <cuda_bf16.h>
#include <math.h>

// Problem constants
#define Tn 128
#define Bn 2048
#define Hn 256
#define In0 18
#define G3H 768

typedef unsigned int u32;

// ---------------- device global scratch ----------------
__device__ float          g_h1f[2][Bn * Hn], g_h2f[2][Bn * Hn];
__device__ __nv_bfloat16  g_h1h[2][Bn * Hn], g_h1l[2][Bn * Hn];
__device__ __nv_bfloat16  g_h2h[2][Bn * Hn], g_h2l[2][Bn * Hn];
__device__ __nv_bfloat16  g_whh0h[G3H * Hn], g_whh0l[G3H * Hn];
__device__ __nv_bfloat16  g_wih1h[G3H * Hn], g_wih1l[G3H * Hn];
__device__ __nv_bfloat16  g_whh1h[G3H * Hn], g_whh1l[G3H * Hn];
__device__ float          g_xg[(size_t)Tn * Bn * G3H];   // precomputed x @ Wih0^T

__device__ __forceinline__ float sigf(float x) { return 1.f / (1.f + expf(-x)); }

// ---------------- PTX helpers ----------------
__device__ __forceinline__ u32 s2u(const void* p) { return (u32)__cvta_generic_to_shared(p); }

__device__ __forceinline__ void ldsm4(u32 (&d)[4], u32 addr) {
    asm volatile("ldmatrix.sync.aligned.m8n8.x4.shared.b16 {%0,%1,%2,%3}, [%4];"
                 : "=r"(d[0]), "=r"(d[1]), "=r"(d[2]), "=r"(d[3]) : "r"(addr));
}
__device__ __forceinline__ void cpa(u32 dst, const void* src) {
    asm volatile("cp.async.cg.shared.global [%0], [%1], 16;" :: "r"(dst), "l"(src));
}
__device__ __forceinline__ void cp_commit_wait() {
    asm volatile("cp.async.commit_group;");
    asm volatile("cp.async.wait_group 0;");
}
__device__ __forceinline__ void mma(float (&d)[4], const u32 (&a)[4], u32 b0, u32 b1) {
    asm("mma.sync.aligned.m16n8k16.row.col.f32.bf16.bf16.f32 "
        "{%0,%1,%2,%3},{%4,%5,%6,%7},{%8,%9},{%0,%1,%2,%3};"
        : "+f"(d[0]), "+f"(d[1]), "+f"(d[2]), "+f"(d[3])
        : "r"(a[0]), "r"(a[1]), "r"(a[2]), "r"(a[3]), "r"(b0), "r"(b1));
}

// ---------------- 64x192xK256 split-bf16 stream ----------------
// A: [b0..b0+63][256] bf16 hi/lo.  W: [768][256] bf16 hi/lo (rows gate*256+j).
// CTA 256 thr = 8 warps (2m x 4n); warp = m32 (mt2) x 48 cols (per gate: units wn*16..+16).
// smem (64KB): sAh[64*128] sAl sWh[192*128] sWl, SW128-swizzled, staged per k64 chunk.
__device__ __forceinline__ void stream64(
    const __nv_bfloat16* __restrict__ Ah, const __nv_bfloat16* __restrict__ Al,
    const __nv_bfloat16* __restrict__ Wh, const __nv_bfloat16* __restrict__ Wl,
    int b0, int j0, char* sm,
    float (&aR)[2][2][4], float (&aZ)[2][2][4], float (&aN)[2][2][4])
{
    const u32 sAh = s2u(sm);
    const u32 sAl = sAh + 64 * 128;
    const u32 sWh = sAl + 64 * 128;
    const u32 sWl = sWh + 192 * 128;
    const int tid = threadIdx.x, lane = tid & 31, wid = tid >> 5;
    const int wm = wid >> 2, wn = wid & 3;

    const int arow_f = (lane & 7) + ((lane >> 3) & 1) * 8;   // A: rows 0-7,k0 | 8-15,k0 | 0-7,k8 | 8-15,k8
    const int akg_f  = (lane >> 4) & 1;
    const int brow_f = (lane & 7) + ((lane >> 4) & 1) * 8;   // B: n0-7,k0 | n0-7,k8 | n8-15,k0 | n8-15,k8
    const int bkg_f  = (lane >> 3) & 1;

    for (int c = 0; c < 4; ++c) {
        __syncthreads();
        // stage A (512 16B-slots per half, 2/thread)
        #pragma unroll
        for (int i = 0; i < 2; ++i) {
            const int idx = tid + i * 256;
            const int r = idx >> 3, g = idx & 7;
            const u32 off = (u32)((r * 8 + (g ^ (r & 7))) * 16);
            const size_t go = (size_t)(b0 + r) * Hn + c * 64 + g * 8;
            cpa(sAh + off, Ah + go);
            cpa(sAl + off, Al + go);
        }
        // stage W (1536 slots per half, 6/thread)
        #pragma unroll
        for (int i = 0; i < 6; ++i) {
            const int idx = tid + i * 256;
            const int cl = idx >> 3, g = idx & 7;
            const int grow = (cl >> 6) * Hn + j0 + (cl & 63);
            const u32 off = (u32)((cl * 8 + (g ^ (cl & 7))) * 16);
            const size_t go = (size_t)grow * Hn + c * 64 + g * 8;
            cpa(sWh + off, Wh + go);
            cpa(sWl + off, Wl + go);
        }
        cp_commit_wait();
        __syncthreads();

        #pragma unroll
        for (int s = 0; s < 4; ++s) {
            u32 ah[2][4], al[2][4];
            #pragma unroll
            for (int mt = 0; mt < 2; ++mt) {
                const int r = wm * 32 + mt * 16 + arow_f;
                const int g = s * 2 + akg_f;
                const u32 off = (u32)((r * 8 + (g ^ (r & 7))) * 16);
                ldsm4(ah[mt], sAh + off);
                ldsm4(al[mt], sAl + off);
            }
            #pragma unroll
            for (int g3 = 0; g3 < 3; ++g3) {
                const int cl = g3 * 64 + wn * 16 + brow_f;
                const int g = s * 2 + bkg_f;
                const u32 off = (u32)((cl * 8 + (g ^ (cl & 7))) * 16);
                u32 bh[4], bl[4];
                ldsm4(bh, sWh + off);
                ldsm4(bl, sWl + off);
                float (*acc)[2][4] = (g3 == 0) ? aR : (g3 == 1) ? aZ : aN;
                // 3 passes: hi*hi, lo*hi, hi*lo; 4 independent accs between reuse
                #pragma unroll
                for (int p = 0; p < 3; ++p) {
                    const u32 (*aa)[4] = (p == 1) ? al : ah;
                    const u32* bb = (p == 2) ? bl : bh;
                    #pragma unroll
                    for (int mt = 0; mt < 2; ++mt) {
                        mma(acc[mt][0], aa[mt], bb[0], bb[1]);
                        mma(acc[mt][1], aa[mt], bb[2], bb[3]);
                    }
                }
            }
        }
    }
}

// ---------------- pipelined super-step ----------------
// CTAs 0..127: layer0 at t=l (M64 tiles, 1 stream; x-part from g_xg).
// CTAs 128..255: layer1 at t=l-1 (M64 tiles, 2 streams).
__global__ void __launch_bounds__(256, 2)
gru_step(const float* __restrict__ bih0, const float* __restrict__ bhh0,
         const float* __restrict__ bih1, const float* __restrict__ bhh1, int l)
{
    extern __shared__ char sm[];
    const int cta = blockIdx.x;
    const int tid = threadIdx.x, lane = tid & 31, wid = tid >> 5;
    const int wm = wid >> 2, wn = wid & 3;

    if (cta < 128) {
        const int t = l;
        if (t >= Tn) return;
        const int b0 = (cta >> 2) * 64, j0 = (cta & 3) * 64;
        const int pv = (t + 1) & 1, cu = t & 1;
        float aR[2][2][4] = {}, aZ[2][2][4] = {}, aN[2][2][4] = {};
        stream64(g_h1h[pv], g_h1l[pv], g_whh0h, g_whh0l, b0, j0, sm, aR, aZ, aN);

        const float* xg = g_xg + (size_t)t * Bn * G3H;
        const float* hpf = g_h1f[pv];
        float* hof = g_h1f[cu];
        __nv_bfloat16* hoh = g_h1h[cu];
        __nv_bfloat16* hol = g_h1l[cu];
        #pragma unroll
        for (int mt = 0; mt < 2; ++mt)
        #pragma unroll
        for (int rr = 0; rr < 2; ++rr) {
            const int b = b0 + wm * 32 + mt * 16 + (lane >> 2) + rr * 8;
            const float* xgb = xg + (size_t)b * G3H;
            #pragma unroll
            for (int nt = 0; nt < 2; ++nt)
            #pragma unroll
            for (int jj = 0; jj < 2; ++jj) {
                const int j = j0 + wn * 16 + nt * 8 + (lane & 3) * 2 + jj;
                const int o = rr * 2 + jj;
                const float r = sigf(xgb[j] + aR[mt][nt][o] + bih0[j] + bhh0[j]);
                const float z = sigf(xgb[256 + j] + aZ[mt][nt][o] + bih0[256 + j] + bhh0[256 + j]);
                const float n = tanhf(xgb[512 + j] + bih0[512 + j] + r * (aN[mt][nt][o] + bhh0[512 + j]));
                const float hp = hpf[(size_t)b * Hn + j];
                const float h = (1.f - z) * n + z * hp;
                hof[(size_t)b * Hn + j] = h;
                const __nv_bfloat16 hh = __float2bfloat16(h);
                hoh[(size_t)b * Hn + j] = hh;
                hol[(size_t)b * Hn + j] = __float2bfloat16(h - __bfloat162float(hh));
            }
        }
    } else {
        const int t = l - 1;
        if (t < 0) return;
        const int idx = cta - 128;
        const int b0 = (idx >> 2) * 64, j0 = (idx & 3) * 64;
        const int pv = (t + 1) & 1, cu = t & 1;
        float aR[2][2][4] = {}, aZ[2][2][4] = {}, aXN[2][2][4] = {}, aHN[2][2][4] = {};
        // x-stream: h1[t] @ Wih1  (r,z accumulate; n -> aXN)
        stream64(g_h1h[cu], g_h1l[cu], g_wih1h, g_wih1l, b0, j0, sm, aR, aZ, aXN);
        // h-stream: h2[t-1] @ Whh1 (r,z accumulate; n -> aHN)
        stream64(g_h2h[pv], g_h2l[pv], g_whh1h, g_whh1l, b0, j0, sm, aR, aZ, aHN);

        const float* hpf = g_h2f[pv];
        float* hof = g_h2f[cu];
        __nv_bfloat16* hoh = g_h2h[cu];
        __nv_bfloat16* hol = g_h2l[cu];
        #pragma unroll
        for (int mt = 0; mt < 2; ++mt)
        #pragma unroll
        for (int rr = 0; rr < 2; ++rr) {
            const int b = b0 + wm * 32 + mt * 16 + (lane >> 2) + rr * 8;
            #pragma unroll
            for (int nt = 0; nt < 2; ++nt)
            #pragma unroll
            for (int jj = 0; jj < 2; ++jj) {
                const int j = j0 + wn * 16 + nt * 8 + (lane & 3) * 2 + jj;
                const int o = rr * 2 + jj;
                const float r = sigf(aR[mt][nt][o] + bih1[j] + bhh1[j]);
                const float z = sigf(aZ[mt][nt][o] + bih1[256 + j] + bhh1[256 + j]);
                const float n = tanhf(aXN[mt][nt][o] + bih1[512 + j] + r * (aHN[mt][nt][o] + bhh1[512 + j]));
                const float hp = hpf[(size_t)b * Hn + j];
                const float h = (1.f - z) * n + z * hp;
                hof[(size_t)b * Hn + j] = h;
                const __nv_bfloat16 hh = __float2bfloat16(h);
                hoh[(size_t)b * Hn + j] = hh;
                hol[(size_t)b * Hn + j] = __float2bfloat16(h - __bfloat162float(hh));
            }
        }
    }
}

// ---------------- prologue: xg = x @ Wih0^T (fp32) ----------------
// block: 256 thr = 8 warps; each warp does 8 rows; W^T cached in smem [18][772].
__global__ void xg_gemm(const float* __restrict__ x, const float* __restrict__ Wih0,
                        float* __restrict__ xg)
{
    extern __shared__ float sW[];
    for (int i = threadIdx.x; i < G3H * In0; i += 256) {
        const int c = i / In0, k = i - c * In0;
        sW[k * 772 + c] = Wih0[i];
    }
    __syncthreads();
    const int lane = threadIdx.x & 31, w = threadIdx.x >> 5;
    for (int it = 0; it < 8; ++it) {
        const size_t row = (size_t)blockIdx.x * 64 + w * 8 + it;
        const float* xr = x + row * In0;
        float xv[In0];
        #pragma unroll
        for (int k = 0; k < In0; ++k) xv[k] = __ldg(xr + k);
        #pragma unroll
        for (int cb = 0; cb < 6; ++cb) {
            const int c = cb * 128 + lane * 4;
            float4 a = make_float4(0.f, 0.f, 0.f, 0.f);
            #pragma unroll
            for (int k = 0; k < In0; ++k) {
                const float4 w4 = *(const float4*)&sW[k * 772 + c];
                a.x = fmaf(xv[k], w4.x, a.x);
                a.y = fmaf(xv[k], w4.y, a.y);
                a.z = fmaf(xv[k], w4.z, a.z);
                a.w = fmaf(xv[k], w4.w, a.w);
            }
            *(float4*)&xg[row * G3H + c] = a;
        }
    }
}

// ---------------- prologue: fp32 -> bf16 hi/lo split ----------------
__global__ void split_plain(const float* __restrict__ src,
                            __nv_bfloat16* __restrict__ hi, __nv_bfloat16* __restrict__ lo, int n)
{
    const int i = blockIdx.x * blockDim.x + threadIdx.x;
    if (i >= n) return;
    const float v = src[i];
    const __nv_bfloat16 h = __float2bfloat16(v);
    hi[i] = h;
    lo[i] = __float2bfloat16(v - __bfloat162float(h));
}

// ---------------- final FC + sigmoid*2-1 ----------------
__global__ void fc_kernel(const float* __restrict__ fcw, const float* __restrict__ fcb,
                          float* __restrict__ out)
{
    const int warp = (blockIdx.x * blockDim.x + threadIdx.x) >> 5;
    const int lane = threadIdx.x & 31;
    if (warp >= Bn) return;
    const float* h = g_h2f[(Tn - 1) & 1] + (size_t)warp * Hn;
    float a0 = 0.f, a1 = 0.f, a2 = 0.f, a3 = 0.f;
    for (int k = lane; k < Hn; k += 32) {
        const float hv = h[k];
        a0 = fmaf(hv, fcw[k], a0);
        a1 = fmaf(hv, fcw[Hn + k], a1);
        a2 = fmaf(hv, fcw[2 * Hn + k], a2);
        a3 = fmaf(hv, fcw[3 * Hn + k], a3);
    }
    #pragma unroll
    for (int s = 16; s; s >>= 1) {
        a0 += __shfl_xor_sync(0xFFFFFFFFu, a0, s);
        a1 += __shfl_xor_sync(0xFFFFFFFFu, a1, s);
        a2 += __shfl_xor_sync(0xFFFFFFFFu, a2, s);
        a3 += __shfl_xor_sync(0xFFFFFFFFu, a3, s);
    }
    if (lane == 0) {
        out[warp * 4 + 0] = 2.f * sigf(a0 + fcb[0]) - 1.f;
        out[warp * 4 + 1] = 2.f * sigf(a1 + fcb[1]) - 1.f;
        out[warp * 4 + 2] = 2.f * sigf(a2 + fcb[2]) - 1.f;
        out[warp * 4 + 3] = 2.f * sigf(a3 + fcb[3]) - 1.f;
    }
}

extern "C" void kernel_launch(void* const* d_in, const int* in_sizes, int n_in,
                              void* d_out, int out_size)
{
    const float* x    = (const float*)d_in[0];
    const float* Wih0 = (const float*)d_in[1];
    const float* Whh0 = (const float*)d_in[2];
    const float* bih0 = (const float*)d_in[3];
    const float* bhh0 = (const float*)d_in[4];
    const float* Wih1 = (const float*)d_in[5];
    const float* Whh1 = (const float*)d_in[6];
    const float* bih1 = (const float*)d_in[7];
    const float* bhh1 = (const float*)d_in[8];
    const float* fcw  = (const float*)d_in[9];
    const float* fcb  = (const float*)d_in[10];
    float* out = (float*)d_out;
    (void)in_sizes; (void)n_in; (void)out_size;

    cudaFuncSetAttribute(gru_step, cudaFuncAttributeMaxDynamicSharedMemorySize, 65536);
    cudaFuncSetAttribute(xg_gemm, cudaFuncAttributeMaxDynamicSharedMemorySize, 57344);

    // weight splits
    {
        void *a, *b;
        const int nw = G3H * Hn;
        cudaGetSymbolAddress(&a, g_whh0h); cudaGetSymbolAddress(&b, g_whh0l);
        split_plain<<<(nw + 255) / 256, 256>>>(Whh0, (__nv_bfloat16*)a, (__nv_bfloat16*)b, nw);
        cudaGetSymbolAddress(&a, g_wih1h); cudaGetSymbolAddress(&b, g_wih1l);
        split_plain<<<(nw + 255) / 256, 256>>>(Wih1, (__nv_bfloat16*)a, (__nv_bfloat16*)b, nw);
        cudaGetSymbolAddress(&a, g_whh1h); cudaGetSymbolAddress(&b, g_whh1l);
        split_plain<<<(nw + 255) / 256, 256>>>(Whh1, (__nv_bfloat16*)a, (__nv_bfloat16*)b, nw);
    }
    // xg precompute: 262144 rows / 64 per block
    {
        void* p; cudaGetSymbolAddress(&p, g_xg);
        xg_gemm<<<(Tn * Bn) / 64, 256, 18 * 772 * 4>>>(x, Wih0, (float*)p);
    }
    // zero ring slot 1 (the t=0 "previous" state)
    {
        void* p;
        const size_t nf = sizeof(float) * (size_t)Bn * Hn;
        const size_t nb = sizeof(__nv_bfloat16) * (size_t)Bn * Hn;
        cudaGetSymbolAddress(&p, g_h1f); cudaMemsetAsync((char*)p + nf, 0, nf, 0);
        cudaGetSymbolAddress(&p, g_h2f); cudaMemsetAsync((char*)p + nf, 0, nf, 0);
        cudaGetSymbolAddress(&p, g_h1h); cudaMemsetAsync((char*)p + nb, 0, nb, 0);
        cudaGetSymbolAddress(&p, g_h1l); cudaMemsetAsync((char*)p + nb, 0, nb, 0);
        cudaGetSymbolAddress(&p, g_h2h); cudaMemsetAsync((char*)p + nb, 0, nb, 0);
        cudaGetSymbolAddress(&p, g_h2l); cudaMemsetAsync((char*)p + nb, 0, nb, 0);
    }

    for (int l = 0; l <= Tn; ++l) {
        gru_step<<<256, 256, 65536>>>(bih0, bhh0, bih1, bhh1, l);
    }

    fc_kernel<<<(Bn * 32) / 256, 256>>>(fcw, fcb, out);
}

// round 9
// speedup vs baseline: 3.2298x; 1.2022x over previous
#include <cuda_runtime.h>
#include <cuda_bf16.h>
#include <math.h>

#define Tn 128
#define Bn 2048
#define Hn 256
#define In0 18
#define G3H 768
#define XP 64          // x K padded to one 64-chunk

typedef unsigned int u32;

// ---------------- device global scratch ----------------
__device__ float          g_h1f[2][Bn * Hn], g_h2f[2][Bn * Hn];
__device__ __nv_bfloat16  g_h1h[2][Bn * Hn], g_h1l[2][Bn * Hn];
__device__ __nv_bfloat16  g_h2h[2][Bn * Hn], g_h2l[2][Bn * Hn];
__device__ __nv_bfloat16  g_whh0h[G3H * Hn], g_whh0l[G3H * Hn];
__device__ __nv_bfloat16  g_wih1h[G3H * Hn], g_wih1l[G3H * Hn];
__device__ __nv_bfloat16  g_whh1h[G3H * Hn], g_whh1l[G3H * Hn];
__device__ __nv_bfloat16  g_wi0h[G3H * XP],  g_wi0l[G3H * XP];    // Wih0 padded 18->64
__device__ __nv_bfloat16  g_xsh[(size_t)Tn * Bn * XP], g_xsl[(size_t)Tn * Bn * XP];

__device__ __forceinline__ float sigf(float x) { return 1.f / (1.f + expf(-x)); }

// ---------------- PTX helpers ----------------
__device__ __forceinline__ u32 s2u(const void* p) { return (u32)__cvta_generic_to_shared(p); }
__device__ __forceinline__ void ldsm4(u32 (&d)[4], u32 addr) {
    asm volatile("ldmatrix.sync.aligned.m8n8.x4.shared.b16 {%0,%1,%2,%3}, [%4];"
                 : "=r"(d[0]), "=r"(d[1]), "=r"(d[2]), "=r"(d[3]) : "r"(addr));
}
__device__ __forceinline__ void cpa(u32 dst, const void* src) {
    asm volatile("cp.async.cg.shared.global [%0], [%1], 16;" :: "r"(dst), "l"(src));
}
__device__ __forceinline__ void mma(float (&d)[4], const u32 (&a)[4], u32 b0, u32 b1) {
    asm("mma.sync.aligned.m16n8k16.row.col.f32.bf16.bf16.f32 "
        "{%0,%1,%2,%3},{%4,%5,%6,%7},{%8,%9},{%0,%1,%2,%3};"
        : "+f"(d[0]), "+f"(d[1]), "+f"(d[2]), "+f"(d[3])
        : "r"(a[0]), "r"(a[1]), "r"(a[2]), "r"(a[3]), "r"(b0), "r"(b1));
}

// smem: 2 buffers x 64KB. Each buffer: A hi 8KB | A lo 8KB | W hi 24KB | W lo 24KB.
#define BUFB 65536
#define SMEM_DYN (2 * BUFB)

// ---------------- chunk staging ----------------
__device__ __forceinline__ void stage_chunk(
    u32 base, int tid, int j0,
    const __nv_bfloat16* __restrict__ Ah, const __nv_bfloat16* __restrict__ Al, int lda,
    const __nv_bfloat16* __restrict__ Wh, const __nv_bfloat16* __restrict__ Wl, int ldw)
{
    const u32 aH = base, aL = base + 8192, wH = base + 16384, wL = base + 40960;
    #pragma unroll
    for (int i = 0; i < 2; ++i) {                     // A: 64 rows x 8 quads
        const int idx = tid + i * 256;
        const int r = idx >> 3, q = idx & 7;
        const u32 off = (u32)((r * 8 + (q ^ (r & 7))) * 16);
        cpa(aH + off, Ah + (size_t)r * lda + q * 8);
        cpa(aL + off, Al + (size_t)r * lda + q * 8);
    }
    #pragma unroll
    for (int i = 0; i < 6; ++i) {                     // W: 192 rows x 8 quads
        const int idx = tid + i * 256;
        const int cl = idx >> 3, q = idx & 7;
        const int grow = (cl >> 6) * Hn + j0 + (cl & 63);
        const u32 off = (u32)((cl * 8 + (q ^ (cl & 7))) * 16);
        cpa(wH + off, Wh + (size_t)grow * ldw + q * 8);
        cpa(wL + off, Wl + (size_t)grow * ldw + q * 8);
    }
    asm volatile("cp.async.commit_group;");
}

// ---------------- chunk compute (validated round-6 fragment mapping) ----------------
// acc sets: 0=R, 1=Z, 2=XN, 3=HN; NSEL picks destination for gate n.
template<int NSEL>
__device__ __forceinline__ void compute_chunk(
    u32 base, int lane, int wm, int wn, float (&acc)[4][2][2][4])
{
    const u32 aH = base, aL = base + 8192, wH = base + 16384, wL = base + 40960;
    const int arow_f = (lane & 7) + ((lane >> 3) & 1) * 8;
    const int akg    = (lane >> 4) & 1;
    const int brow_f = (lane & 7) + ((lane >> 4) & 1) * 8;
    const int bkg    = (lane >> 3) & 1;
    #pragma unroll
    for (int s = 0; s < 4; ++s) {
        u32 ah[2][4], al[2][4];
        #pragma unroll
        for (int mt = 0; mt < 2; ++mt) {
            const int r = wm * 32 + mt * 16 + arow_f;
            const int g = s * 2 + akg;
            const u32 off = (u32)((r * 8 + (g ^ (r & 7))) * 16);
            ldsm4(ah[mt], aH + off);
            ldsm4(al[mt], aL + off);
        }
        #pragma unroll
        for (int g3 = 0; g3 < 3; ++g3) {
            const int set = (g3 == 2) ? NSEL : g3;
            const int cl = g3 * 64 + wn * 16 + brow_f;
            const int g = s * 2 + bkg;
            const u32 off = (u32)((cl * 8 + (g ^ (cl & 7))) * 16);
            u32 bh[4], bl[4];
            ldsm4(bh, wH + off);
            ldsm4(bl, wL + off);
            #pragma unroll
            for (int p = 0; p < 3; ++p) {             // hi*hi, lo*hi, hi*lo
                const u32 (*aa)[4] = (p == 1) ? al : ah;
                const u32* bb = (p == 2) ? bl : bh;
                #pragma unroll
                for (int mt = 0; mt < 2; ++mt) {
                    mma(acc[set][mt][0], aa[mt], bb[0], bb[1]);
                    mma(acc[set][mt][1], aa[mt], bb[2], bb[3]);
                }
            }
        }
    }
}

// ---------------- GRU gate epilogue ----------------
__device__ __forceinline__ void epilogue(
    const float* __restrict__ bih, const float* __restrict__ bhh,
    const float* __restrict__ hpf, float* __restrict__ hof,
    __nv_bfloat16* __restrict__ hoh, __nv_bfloat16* __restrict__ hol,
    int b0, int j0, int lane, int wm, int wn, float (&acc)[4][2][2][4])
{
    #pragma unroll
    for (int mt = 0; mt < 2; ++mt)
    #pragma unroll
    for (int rr = 0; rr < 2; ++rr) {
        const int b = b0 + wm * 32 + mt * 16 + (lane >> 2) + rr * 8;
        #pragma unroll
        for (int nt = 0; nt < 2; ++nt) {
            const int jb = j0 + wn * 16 + nt * 8 + (lane & 3) * 2;
            float hv[2];
            #pragma unroll
            for (int jj = 0; jj < 2; ++jj) {
                const int j = jb + jj;
                const int o = rr * 2 + jj;
                const float r = sigf(acc[0][mt][nt][o] + bih[j] + bhh[j]);
                const float z = sigf(acc[1][mt][nt][o] + bih[Hn + j] + bhh[Hn + j]);
                const float n = tanhf(acc[2][mt][nt][o] + bih[2 * Hn + j]
                                      + r * (acc[3][mt][nt][o] + bhh[2 * Hn + j]));
                const float hp = hpf[(size_t)b * Hn + j];
                hv[jj] = (1.f - z) * n + z * hp;
            }
            *(float2*)(hof + (size_t)b * Hn + jb) = make_float2(hv[0], hv[1]);
            const __nv_bfloat16 h0 = __float2bfloat16(hv[0]);
            const __nv_bfloat16 h1 = __float2bfloat16(hv[1]);
            const __nv_bfloat16 l0 = __float2bfloat16(hv[0] - __bfloat162float(h0));
            const __nv_bfloat16 l1 = __float2bfloat16(hv[1] - __bfloat162float(h1));
            *(u32*)(hoh + (size_t)b * Hn + jb) =
                (u32)__bfloat16_as_ushort(h0) | ((u32)__bfloat16_as_ushort(h1) << 16);
            *(u32*)(hol + (size_t)b * Hn + jb) =
                (u32)__bfloat16_as_ushort(l0) | ((u32)__bfloat16_as_ushort(l1) << 16);
        }
    }
}

// ---------------- fused balanced super-step ----------------
// Every CTA: tile (b0:64, j0:64); chunks 0..4 = layer0(t=l) [x-chunk + 4 h-chunks],
// chunks 5..12 = layer1(t=l-1) [4 ih-chunks + 4 hh-chunks]. Uniform work per CTA.
__global__ void __launch_bounds__(256, 1)
gru_step(const float* __restrict__ bih0, const float* __restrict__ bhh0,
         const float* __restrict__ bih1, const float* __restrict__ bhh1, int l)
{
    extern __shared__ char sm[];
    const u32 sb = s2u(sm);
    const int tid = threadIdx.x, lane = tid & 31, wid = tid >> 5;
    const int wm = wid >> 2, wn = wid & 3;
    const int cta = blockIdx.x;
    const int b0 = (cta >> 2) * 64, j0 = (cta & 3) * 64;
    const int pv = (l + 1) & 1, cu = l & 1;

    const int kbeg = (l < Tn) ? 0 : 5;
    const int kend = (l >= 1) ? 13 : 5;

    float acc[4][2][2][4] = {};

    auto src = [&](int k, const __nv_bfloat16*& Ah, const __nv_bfloat16*& Al, int& lda,
                   const __nv_bfloat16*& Wh, const __nv_bfloat16*& Wl, int& ldw) {
        if (k == 0) {
            Ah = g_xsh + ((size_t)l * Bn + b0) * XP;
            Al = g_xsl + ((size_t)l * Bn + b0) * XP;
            lda = XP; Wh = g_wi0h; Wl = g_wi0l; ldw = XP;
        } else if (k <= 4) {
            const int c = k - 1;
            Ah = g_h1h[pv] + (size_t)b0 * Hn + c * 64;
            Al = g_h1l[pv] + (size_t)b0 * Hn + c * 64;
            lda = Hn; Wh = g_whh0h + c * 64; Wl = g_whh0l + c * 64; ldw = Hn;
        } else if (k <= 8) {
            const int c = k - 5;
            Ah = g_h1h[pv] + (size_t)b0 * Hn + c * 64;   // L1 input = h1[t'=l-1], slot pv
            Al = g_h1l[pv] + (size_t)b0 * Hn + c * 64;
            lda = Hn; Wh = g_wih1h + c * 64; Wl = g_wih1l + c * 64; ldw = Hn;
        } else {
            const int c = k - 9;
            Ah = g_h2h[cu] + (size_t)b0 * Hn + c * 64;   // h2[t'-1], slot cu
            Al = g_h2l[cu] + (size_t)b0 * Hn + c * 64;
            lda = Hn; Wh = g_whh1h + c * 64; Wl = g_whh1l + c * 64; ldw = Hn;
        }
    };

    // prime pipeline
    {
        const __nv_bfloat16 *Ah, *Al, *Wh, *Wl; int lda, ldw;
        src(kbeg, Ah, Al, lda, Wh, Wl, ldw);
        stage_chunk(sb, tid, j0, Ah, Al, lda, Wh, Wl, ldw);
    }

    for (int k = kbeg; k < kend; ++k) {
        const int buf = (k - kbeg) & 1;
        __syncthreads();                               // prev compute done; other buf free
        if (k + 1 < kend) {
            const __nv_bfloat16 *Ah, *Al, *Wh, *Wl; int lda, ldw;
            src(k + 1, Ah, Al, lda, Wh, Wl, ldw);
            stage_chunk(sb + (buf ^ 1) * BUFB, tid, j0, Ah, Al, lda, Wh, Wl, ldw);
            asm volatile("cp.async.wait_group 1;");
        } else {
            asm volatile("cp.async.wait_group 0;");
        }
        __syncthreads();

        const u32 base = sb + buf * BUFB;
        const bool toXN = (k == 0) || (k >= 5 && k <= 8);
        if (toXN) compute_chunk<2>(base, lane, wm, wn, acc);
        else      compute_chunk<3>(base, lane, wm, wn, acc);

        if (k == 4) {   // layer0 complete -> h1[cu]
            epilogue(bih0, bhh0, g_h1f[pv], g_h1f[cu], g_h1h[cu], g_h1l[cu],
                     b0, j0, lane, wm, wn, acc);
            #pragma unroll
            for (int a = 0; a < 4; ++a)
            #pragma unroll
            for (int m2 = 0; m2 < 2; ++m2)
            #pragma unroll
            for (int n2 = 0; n2 < 2; ++n2)
            #pragma unroll
            for (int q = 0; q < 4; ++q) acc[a][m2][n2][q] = 0.f;
        }
    }

    if (l >= 1) {   // layer1 complete -> h2[pv]
        epilogue(bih1, bhh1, g_h2f[cu], g_h2f[pv], g_h2h[pv], g_h2l[pv],
                 b0, j0, lane, wm, wn, acc);
    }
}

// ---------------- prologue splits ----------------
__global__ void split_plain(const float* __restrict__ src,
                            __nv_bfloat16* __restrict__ hi, __nv_bfloat16* __restrict__ lo, int n)
{
    const int i = blockIdx.x * blockDim.x + threadIdx.x;
    if (i >= n) return;
    const float v = src[i];
    const __nv_bfloat16 h = __float2bfloat16(v);
    hi[i] = h;
    lo[i] = __float2bfloat16(v - __bfloat162float(h));
}

__global__ void split_pad(const float* __restrict__ src,
                          __nv_bfloat16* __restrict__ hi, __nv_bfloat16* __restrict__ lo,
                          size_t rows)
{
    const size_t i = (size_t)blockIdx.x * blockDim.x + threadIdx.x;
    if (i >= rows * XP) return;
    const size_t r = i >> 6;
    const int k = (int)(i & 63);
    const float v = (k < In0) ? src[r * In0 + k] : 0.f;
    const __nv_bfloat16 h = __float2bfloat16(v);
    hi[i] = h;
    lo[i] = __float2bfloat16(v - __bfloat162float(h));
}

// ---------------- final FC + sigmoid*2-1 ----------------
__global__ void fc_kernel(const float* __restrict__ fcw, const float* __restrict__ fcb,
                          float* __restrict__ out)
{
    const int warp = (blockIdx.x * blockDim.x + threadIdx.x) >> 5;
    const int lane = threadIdx.x & 31;
    if (warp >= Bn) return;
    const float* h = g_h2f[(Tn - 1) & 1] + (size_t)warp * Hn;
    float a0 = 0.f, a1 = 0.f, a2 = 0.f, a3 = 0.f;
    for (int k = lane; k < Hn; k += 32) {
        const float hv = h[k];
        a0 = fmaf(hv, fcw[k], a0);
        a1 = fmaf(hv, fcw[Hn + k], a1);
        a2 = fmaf(hv, fcw[2 * Hn + k], a2);
        a3 = fmaf(hv, fcw[3 * Hn + k], a3);
    }
    #pragma unroll
    for (int s = 16; s; s >>= 1) {
        a0 += __shfl_xor_sync(0xFFFFFFFFu, a0, s);
        a1 += __shfl_xor_sync(0xFFFFFFFFu, a1, s);
        a2 += __shfl_xor_sync(0xFFFFFFFFu, a2, s);
        a3 += __shfl_xor_sync(0xFFFFFFFFu, a3, s);
    }
    if (lane == 0) {
        out[warp * 4 + 0] = 2.f * sigf(a0 + fcb[0]) - 1.f;
        out[warp * 4 + 1] = 2.f * sigf(a1 + fcb[1]) - 1.f;
        out[warp * 4 + 2] = 2.f * sigf(a2 + fcb[2]) - 1.f;
        out[warp * 4 + 3] = 2.f * sigf(a3 + fcb[3]) - 1.f;
    }
}

extern "C" void kernel_launch(void* const* d_in, const int* in_sizes, int n_in,
                              void* d_out, int out_size)
{
    const float* x    = (const float*)d_in[0];
    const float* Wih0 = (const float*)d_in[1];
    const float* Whh0 = (const float*)d_in[2];
    const float* bih0 = (const float*)d_in[3];
    const float* bhh0 = (const float*)d_in[4];
    const float* Wih1 = (const float*)d_in[5];
    const float* Whh1 = (const float*)d_in[6];
    const float* bih1 = (const float*)d_in[7];
    const float* bhh1 = (const float*)d_in[8];
    const float* fcw  = (const float*)d_in[9];
    const float* fcb  = (const float*)d_in[10];
    float* out = (float*)d_out;
    (void)in_sizes; (void)n_in; (void)out_size;

    cudaFuncSetAttribute(gru_step, cudaFuncAttributeMaxDynamicSharedMemorySize, SMEM_DYN);

    // weight hi/lo splits
    {
        void *a, *b;
        const int nw = G3H * Hn;
        cudaGetSymbolAddress(&a, g_whh0h); cudaGetSymbolAddress(&b, g_whh0l);
        split_plain<<<(nw + 255) / 256, 256>>>(Whh0, (__nv_bfloat16*)a, (__nv_bfloat16*)b, nw);
        cudaGetSymbolAddress(&a, g_wih1h); cudaGetSymbolAddress(&b, g_wih1l);
        split_plain<<<(nw + 255) / 256, 256>>>(Wih1, (__nv_bfloat16*)a, (__nv_bfloat16*)b, nw);
        cudaGetSymbolAddress(&a, g_whh1h); cudaGetSymbolAddress(&b, g_whh1l);
        split_plain<<<(nw + 255) / 256, 256>>>(Whh1, (__nv_bfloat16*)a, (__nv_bfloat16*)b, nw);
        // padded Wih0 (18 -> 64 cols)
        cudaGetSymbolAddress(&a, g_wi0h); cudaGetSymbolAddress(&b, g_wi0l);
        split_pad<<<(G3H * XP + 255) / 256, 256>>>(Wih0, (__nv_bfloat16*)a, (__nv_bfloat16*)b, G3H);
        // padded x (18 -> 64 cols), all timesteps
        cudaGetSymbolAddress(&a, g_xsh); cudaGetSymbolAddress(&b, g_xsl);
        const size_t rows = (size_t)Tn * Bn;
        split_pad<<<(unsigned)((rows * XP + 255) / 256), 256>>>(x, (__nv_bfloat16*)a,
                                                                (__nv_bfloat16*)b, rows);
    }
    // zero ring slot 1 ("previous" state at t=0 for both layers)
    {
        void* p;
        const size_t nf = sizeof(float) * (size_t)Bn * Hn;
        const size_t nb = sizeof(__nv_bfloat16) * (size_t)Bn * Hn;
        cudaGetSymbolAddress(&p, g_h1f); cudaMemsetAsync((char*)p + nf, 0, nf, 0);
        cudaGetSymbolAddress(&p, g_h2f); cudaMemsetAsync((char*)p + nf, 0, nf, 0);
        cudaGetSymbolAddress(&p, g_h1h); cudaMemsetAsync((char*)p + nb, 0, nb, 0);
        cudaGetSymbolAddress(&p, g_h1l); cudaMemsetAsync((char*)p + nb, 0, nb, 0);
        cudaGetSymbolAddress(&p, g_h2h); cudaMemsetAsync((char*)p + nb, 0, nb, 0);
        cudaGetSymbolAddress(&p, g_h2l); cudaMemsetAsync((char*)p + nb, 0, nb, 0);
    }

    for (int l = 0; l <= Tn; ++l) {
        gru_step<<<128, 256, SMEM_DYN>>>(bih0, bhh0, bih1, bhh1, l);
    }

    fc_kernel<<<(Bn * 32) / 256, 256>>>(fcw, fcb, out);
}

// round 12
// speedup vs baseline: 3.6780x; 1.1388x over previous
#include <cuda_runtime.h>
#include <cuda_bf16.h>
#include <math.h>

#define Tn 128
#define Bn 2048
#define Hn 256
#define In0 18
#define G3H 768
#define XP 32          // x K padded to 32 (one half-chunk)

typedef unsigned int u32;

// ---------------- device global scratch ----------------
__device__ float          g_h1f[2][Bn * Hn], g_h2f[2][Bn * Hn];
__device__ __nv_bfloat16  g_h1h[2][Bn * Hn], g_h1l[2][Bn * Hn];
__device__ __nv_bfloat16  g_h2h[2][Bn * Hn], g_h2l[2][Bn * Hn];
__device__ __nv_bfloat16  g_whh0h[G3H * Hn], g_whh0l[G3H * Hn];
__device__ __nv_bfloat16  g_wih1h[G3H * Hn], g_wih1l[G3H * Hn];
__device__ __nv_bfloat16  g_whh1h[G3H * Hn], g_whh1l[G3H * Hn];
__device__ __nv_bfloat16  g_wi0h[G3H * XP],  g_wi0l[G3H * XP];
__device__ __nv_bfloat16  g_xsh[(size_t)Tn * Bn * XP], g_xsl[(size_t)Tn * Bn * XP];
__device__ unsigned       g_bar[32];

__device__ __forceinline__ float sigf(float x) { return 1.f / (1.f + expf(-x)); }
__device__ __forceinline__ float tanha(float x) {
    float y; asm("tanh.approx.f32 %0, %1;" : "=f"(y) : "f"(x)); return y;
}
__device__ __forceinline__ float siga(float x) { return fmaf(tanha(0.5f * x), 0.5f, 0.5f); }

// ---------------- PTX helpers ----------------
__device__ __forceinline__ u32 s2u(const void* p) { return (u32)__cvta_generic_to_shared(p); }
__device__ __forceinline__ void ldsm4(u32 (&d)[4], u32 addr) {
    asm volatile("ldmatrix.sync.aligned.m8n8.x4.shared.b16 {%0,%1,%2,%3}, [%4];"
                 : "=r"(d[0]), "=r"(d[1]), "=r"(d[2]), "=r"(d[3]) : "r"(addr));
}
__device__ __forceinline__ void cpa(u32 dst, const void* src) {
    asm volatile("cp.async.cg.shared.global [%0], [%1], 16;" :: "r"(dst), "l"(src));
}
__device__ __forceinline__ void mma(float (&d)[4], const u32 (&a)[4], u32 b0, u32 b1) {
    asm("mma.sync.aligned.m16n8k16.row.col.f32.bf16.bf16.f32 "
        "{%0,%1,%2,%3},{%4,%5,%6,%7},{%8,%9},{%0,%1,%2,%3};"
        : "+f"(d[0]), "+f"(d[1]), "+f"(d[2]), "+f"(d[3])
        : "r"(a[0]), "r"(a[1]), "r"(a[2]), "r"(a[3]), "r"(b0), "r"(b1));
}

// smem: 2 buffers x 64KB. Buffer: A hi | A lo | (16KB pad) W hi | W lo.
#define BUFB 65536
#define SMEM_DYN (2 * BUFB)

// ---------------- staging (QW = 16B quads per row: 8 => K64, 4 => K32) ----------------
template<int QW>
__device__ __forceinline__ void stage_chunk(
    u32 base, int tid, int j0,
    const __nv_bfloat16* __restrict__ Ah, const __nv_bfloat16* __restrict__ Al, int lda,
    const __nv_bfloat16* __restrict__ Wh, const __nv_bfloat16* __restrict__ Wl, int ldw)
{
    const u32 aH = base, aL = base + QW * 1024;
    const u32 wH = base + 16384, wL = wH + QW * 192 * 16;
    #pragma unroll
    for (int i = 0; i < (64 * QW) / 256; ++i) {
        const int idx = tid + i * 256;
        const int r = idx / QW, q = idx % QW;
        const u32 off = (u32)((r * QW + (q ^ (r & (QW - 1)))) * 16);
        cpa(aH + off, Ah + (size_t)r * lda + q * 8);
        cpa(aL + off, Al + (size_t)r * lda + q * 8);
    }
    #pragma unroll
    for (int i = 0; i < (192 * QW) / 256; ++i) {
        const int idx = tid + i * 256;
        const int cl = idx / QW, q = idx % QW;
        const int grow = (cl >> 6) * Hn + j0 + (cl & 63);
        const u32 off = (u32)((cl * QW + (q ^ (cl & (QW - 1)))) * 16);
        cpa(wH + off, Wh + (size_t)grow * ldw + q * 8);
        cpa(wL + off, Wl + (size_t)grow * ldw + q * 8);
    }
    asm volatile("cp.async.commit_group;");
}

// resolve chunk source & stage. k: 0=x-chunk(QW4), 1..4 whh0, 5..8 wih1, 9..12 whh1.
__device__ __forceinline__ void stage_any(int k, int l, u32 base, int tid, int b0, int j0)
{
    const int pv = (l + 1) & 1, cu = l & 1;
    if (k == 0) {
        stage_chunk<4>(base, tid, j0,
                       g_xsh + ((size_t)l * Bn + b0) * XP, g_xsl + ((size_t)l * Bn + b0) * XP, XP,
                       g_wi0h, g_wi0l, XP);
    } else if (k <= 4) {
        const int c = k - 1;
        stage_chunk<8>(base, tid, j0,
                       g_h1h[pv] + (size_t)b0 * Hn + c * 64, g_h1l[pv] + (size_t)b0 * Hn + c * 64, Hn,
                       g_whh0h + c * 64, g_whh0l + c * 64, Hn);
    } else if (k <= 8) {
        const int c = k - 5;
        stage_chunk<8>(base, tid, j0,
                       g_h1h[pv] + (size_t)b0 * Hn + c * 64, g_h1l[pv] + (size_t)b0 * Hn + c * 64, Hn,
                       g_wih1h + c * 64, g_wih1l + c * 64, Hn);
    } else {
        const int c = k - 9;
        stage_chunk<8>(base, tid, j0,
                       g_h2h[cu] + (size_t)b0 * Hn + c * 64, g_h2l[cu] + (size_t)b0 * Hn + c * 64, Hn,
                       g_whh1h + c * 64, g_whh1l + c * 64, Hn);
    }
}

// ---------------- compute (acc sets: 0=R 1=Z 2=XN 3=HN; NSEL = dest for gate n) ----------------
template<int QW, int NSEL>
__device__ __forceinline__ void compute_chunk(
    u32 base, int lane, int wm, int wn, float (&acc)[4][2][2][4])
{
    const u32 aH = base, aL = base + QW * 1024;
    const u32 wH = base + 16384, wL = wH + QW * 192 * 16;
    const int arow_f = (lane & 7) + ((lane >> 3) & 1) * 8;
    const int akg    = (lane >> 4) & 1;
    const int brow_f = (lane & 7) + ((lane >> 4) & 1) * 8;
    const int bkg    = (lane >> 3) & 1;
    #pragma unroll
    for (int s = 0; s < QW / 2; ++s) {
        u32 ah[2][4], al[2][4];
        #pragma unroll
        for (int mt = 0; mt < 2; ++mt) {
            const int r = wm * 32 + mt * 16 + arow_f;
            const int g = s * 2 + akg;
            const u32 off = (u32)((r * QW + (g ^ (r & (QW - 1)))) * 16);
            ldsm4(ah[mt], aH + off);
            ldsm4(al[mt], aL + off);
        }
        #pragma unroll
        for (int g3 = 0; g3 < 3; ++g3) {
            const int set = (g3 == 2) ? NSEL : g3;
            const int cl = g3 * 64 + wn * 16 + brow_f;
            const int g = s * 2 + bkg;
            const u32 off = (u32)((cl * QW + (g ^ (cl & (QW - 1)))) * 16);
            u32 bh[4], bl[4];
            ldsm4(bh, wH + off);
            ldsm4(bl, wL + off);
            #pragma unroll
            for (int p = 0; p < 3; ++p) {             // hi*hi, lo*hi, hi*lo
                const u32 (*aa)[4] = (p == 1) ? al : ah;
                const u32* bb = (p == 2) ? bl : bh;
                #pragma unroll
                for (int mt = 0; mt < 2; ++mt) {
                    mma(acc[set][mt][0], aa[mt], bb[0], bb[1]);
                    mma(acc[set][mt][1], aa[mt], bb[2], bb[3]);
                }
            }
        }
    }
}

// ---------------- GRU gate epilogue ----------------
__device__ __forceinline__ void epilogue(
    const float* __restrict__ bih, const float* __restrict__ bhh,
    const float* __restrict__ hpf, float* __restrict__ hof,
    __nv_bfloat16* __restrict__ hoh, __nv_bfloat16* __restrict__ hol,
    int b0, int j0, int lane, int wm, int wn, float (&acc)[4][2][2][4])
{
    #pragma unroll
    for (int mt = 0; mt < 2; ++mt)
    #pragma unroll
    for (int rr = 0; rr < 2; ++rr) {
        const int b = b0 + wm * 32 + mt * 16 + (lane >> 2) + rr * 8;
        #pragma unroll
        for (int nt = 0; nt < 2; ++nt) {
            const int jb = j0 + wn * 16 + nt * 8 + (lane & 3) * 2;
            float hv[2];
            #pragma unroll
            for (int jj = 0; jj < 2; ++jj) {
                const int j = jb + jj;
                const int o = rr * 2 + jj;
                const float r = siga(acc[0][mt][nt][o] + bih[j] + bhh[j]);
                const float z = siga(acc[1][mt][nt][o] + bih[Hn + j] + bhh[Hn + j]);
                const float n = tanha(acc[2][mt][nt][o] + bih[2 * Hn + j]
                                      + r * (acc[3][mt][nt][o] + bhh[2 * Hn + j]));
                const float hp = hpf[(size_t)b * Hn + j];
                hv[jj] = (1.f - z) * n + z * hp;
            }
            *(float2*)(hof + (size_t)b * Hn + jb) = make_float2(hv[0], hv[1]);
            const __nv_bfloat16 h0 = __float2bfloat16(hv[0]);
            const __nv_bfloat16 h1 = __float2bfloat16(hv[1]);
            const __nv_bfloat16 l0 = __float2bfloat16(hv[0] - __bfloat162float(h0));
            const __nv_bfloat16 l1 = __float2bfloat16(hv[1] - __bfloat162float(h1));
            *(u32*)(hoh + (size_t)b * Hn + jb) =
                (u32)__bfloat16_as_ushort(h0) | ((u32)__bfloat16_as_ushort(h1) << 16);
            *(u32*)(hol + (size_t)b * Hn + jb) =
                (u32)__bfloat16_as_ushort(l0) | ((u32)__bfloat16_as_ushort(l1) << 16);
        }
    }
}

// ---------------- persistent scan kernel ----------------
// grid 128, 1 CTA/SM, all resident. Group = 4 CTAs sharing b0; groups independent.
__global__ void __launch_bounds__(256, 1)
gru_scan(const float* __restrict__ bih0, const float* __restrict__ bhh0,
         const float* __restrict__ bih1, const float* __restrict__ bhh1,
         const float* __restrict__ fcw, const float* __restrict__ fcb,
         float* __restrict__ out)
{
    extern __shared__ char sm[];
    const u32 sb = s2u(sm);
    const int tid = threadIdx.x, lane = tid & 31, wid = tid >> 5;
    const int wm = wid >> 2, wn = wid & 3;
    const int cta = blockIdx.x;
    const int grp = cta >> 2, member = cta & 3;
    const int b0 = grp * 64, j0 = member * 64;

    int cc = 0;
    // prime: stage x-chunk of superstep 0
    stage_any(0, 0, sb, tid, b0, j0);

    for (int l = 0; l <= Tn; ++l) {
        const int pv = (l + 1) & 1, cu = l & 1;
        const int kbeg = (l < Tn) ? 0 : 5;
        const int kend = (l >= 1) ? 13 : 5;

        float acc[4][2][2][4] = {};

        if (l == Tn) stage_any(5, l, sb + (cc & 1) * BUFB, tid, b0, j0);  // re-prime

        for (int k = kbeg; k < kend; ++k) {
            const int buf = cc & 1;
            __syncthreads();                         // prev compute done; other buf free
            bool havenext = false;
            if (k + 1 < kend) {
                stage_any(k + 1, l, sb + (buf ^ 1) * BUFB, tid, b0, j0);
                havenext = true;
            } else if (l + 1 <= Tn - 1) {            // prefetch next superstep's x-chunk
                stage_any(0, l + 1, sb + (buf ^ 1) * BUFB, tid, b0, j0);
                havenext = true;
            }
            if (havenext) asm volatile("cp.async.wait_group 1;");
            else          asm volatile("cp.async.wait_group 0;");
            __syncthreads();

            const u32 base = sb + buf * BUFB;
            if (k == 0)      compute_chunk<4, 2>(base, lane, wm, wn, acc);
            else if (k <= 4) compute_chunk<8, 3>(base, lane, wm, wn, acc);
            else if (k <= 8) compute_chunk<8, 2>(base, lane, wm, wn, acc);
            else             compute_chunk<8, 3>(base, lane, wm, wn, acc);

            if (k == 4) {   // layer0 complete -> h1[cu]
                epilogue(bih0, bhh0, g_h1f[pv], g_h1f[cu], g_h1h[cu], g_h1l[cu],
                         b0, j0, lane, wm, wn, acc);
                #pragma unroll
                for (int a = 0; a < 4; ++a)
                #pragma unroll
                for (int m2 = 0; m2 < 2; ++m2)
                #pragma unroll
                for (int n2 = 0; n2 < 2; ++n2)
                #pragma unroll
                for (int q = 0; q < 4; ++q) acc[a][m2][n2][q] = 0.f;
            }
            ++cc;
        }

        if (l >= 1) {   // layer1 (t=l-1) complete -> h2[pv]
            epilogue(bih1, bhh1, g_h2f[cu], g_h2f[pv], g_h2h[pv], g_h2l[pv],
                     b0, j0, lane, wm, wn, acc);
        }

        // ---- group barrier (release-acquire) ----
        __threadfence();
        __syncthreads();
        if (tid == 0) {
            atomicAdd(&g_bar[grp], 1u);
            const unsigned target = 4u * (unsigned)(l + 1);
            while (atomicAdd(&g_bar[grp], 0u) < target) { }
            __threadfence();
        }
        __syncthreads();
    }

    // ---- fc tail: member handles rows b0+member*16 .. +16 ----
    const float* fh = g_h2f[(Tn - 1) & 1];
    for (int rr = wid; rr < 16; rr += 8) {
        const int b = b0 + member * 16 + rr;
        const float* h = fh + (size_t)b * Hn;
        float a0 = 0.f, a1 = 0.f, a2 = 0.f, a3 = 0.f;
        for (int kk = lane; kk < Hn; kk += 32) {
            const float hv = h[kk];
            a0 = fmaf(hv, fcw[kk], a0);
            a1 = fmaf(hv, fcw[Hn + kk], a1);
            a2 = fmaf(hv, fcw[2 * Hn + kk], a2);
            a3 = fmaf(hv, fcw[3 * Hn + kk], a3);
        }
        #pragma unroll
        for (int s = 16; s; s >>= 1) {
            a0 += __shfl_xor_sync(0xFFFFFFFFu, a0, s);
            a1 += __shfl_xor_sync(0xFFFFFFFFu, a1, s);
            a2 += __shfl_xor_sync(0xFFFFFFFFu, a2, s);
            a3 += __shfl_xor_sync(0xFFFFFFFFu, a3, s);
        }
        if (lane == 0) {
            out[b * 4 + 0] = 2.f * sigf(a0 + fcb[0]) - 1.f;
            out[b * 4 + 1] = 2.f * sigf(a1 + fcb[1]) - 1.f;
            out[b * 4 + 2] = 2.f * sigf(a2 + fcb[2]) - 1.f;
            out[b * 4 + 3] = 2.f * sigf(a3 + fcb[3]) - 1.f;
        }
    }
}

// ---------------- prologue: all splits in one kernel ----------------
__global__ void split_all(const float* __restrict__ Whh0, const float* __restrict__ Wih1,
                          const float* __restrict__ Whh1, const float* __restrict__ Wih0,
                          const float* __restrict__ x)
{
    const size_t NW = (size_t)G3H * Hn;           // 196608
    const size_t NI = (size_t)G3H * XP;           // 24576
    const size_t NX = (size_t)Tn * Bn * XP;       // 8388608
    const size_t i = (size_t)blockIdx.x * blockDim.x + threadIdx.x;
    float v; __nv_bfloat16 *hi, *lo; size_t o;
    if (i < NW)            { o = i;            v = Whh0[o]; hi = g_whh0h; lo = g_whh0l; }
    else if (i < 2 * NW)   { o = i - NW;       v = Wih1[o]; hi = g_wih1h; lo = g_wih1l; }
    else if (i < 3 * NW)   { o = i - 2 * NW;   v = Whh1[o]; hi = g_whh1h; lo = g_whh1l; }
    else if (i < 3 * NW + NI) {
        o = i - 3 * NW;
        const size_t r = o >> 5; const int k = (int)(o & 31);
        v = (k < In0) ? Wih0[r * In0 + k] : 0.f; hi = g_wi0h; lo = g_wi0l;
    } else if (i < 3 * NW + NI + NX) {
        o = i - 3 * NW - NI;
        const size_t r = o >> 5; const int k = (int)(o & 31);
        v = (k < In0) ? x[r * In0 + k] : 0.f; hi = g_xsh; lo = g_xsl;
    } else return;
    const __nv_bfloat16 h = __float2bfloat16(v);
    hi[o] = h;
    lo[o] = __float2bfloat16(v - __bfloat162float(h));
}

extern "C" void kernel_launch(void* const* d_in, const int* in_sizes, int n_in,
                              void* d_out, int out_size)
{
    const float* x    = (const float*)d_in[0];
    const float* Wih0 = (const float*)d_in[1];
    const float* Whh0 = (const float*)d_in[2];
    const float* bih0 = (const float*)d_in[3];
    const float* bhh0 = (const float*)d_in[4];
    const float* Wih1 = (const float*)d_in[5];
    const float* Whh1 = (const float*)d_in[6];
    const float* bih1 = (const float*)d_in[7];
    const float* bhh1 = (const float*)d_in[8];
    const float* fcw  = (const float*)d_in[9];
    const float* fcb  = (const float*)d_in[10];
    float* out = (float*)d_out;
    (void)in_sizes; (void)n_in; (void)out_size;

    cudaFuncSetAttribute(gru_scan, cudaFuncAttributeMaxDynamicSharedMemorySize, SMEM_DYN);

    // prologue splits (one kernel)
    {
        const size_t total = 3 * (size_t)G3H * Hn + (size_t)G3H * XP + (size_t)Tn * Bn * XP;
        split_all<<<(unsigned)((total + 255) / 256), 256>>>(Whh0, Wih1, Whh1, Wih0, x);
    }
    // zero barrier counters + ring slot 1 ("previous" state at t=0)
    {
        void* p;
        const size_t nf = sizeof(float) * (size_t)Bn * Hn;
        const size_t nb = sizeof(__nv_bfloat16) * (size_t)Bn * Hn;
        cudaGetSymbolAddress(&p, g_bar); cudaMemsetAsync(p, 0, sizeof(unsigned) * 32, 0);
        cudaGetSymbolAddress(&p, g_h1f); cudaMemsetAsync((char*)p + nf, 0, nf, 0);
        cudaGetSymbolAddress(&p, g_h2f); cudaMemsetAsync((char*)p + nf, 0, nf, 0);
        cudaGetSymbolAddress(&p, g_h1h); cudaMemsetAsync((char*)p + nb, 0, nb, 0);
        cudaGetSymbolAddress(&p, g_h1l); cudaMemsetAsync((char*)p + nb, 0, nb, 0);
        cudaGetSymbolAddress(&p, g_h2h); cudaMemsetAsync((char*)p + nb, 0, nb, 0);
        cudaGetSymbolAddress(&p, g_h2l); cudaMemsetAsync((char*)p + nb, 0, nb, 0);
    }

    gru_scan<<<128, 256, SMEM_DYN>>>(bih0, bhh0, bih1, bhh1, fcw, fcb, out);
}